// round 1
// baseline (speedup 1.0000x reference)
#include <cuda_runtime.h>

#define NN 48000          // NUM_NODES * WINDOW
#define NODES 2000
#define WIN 24
#define EE 768000
#define FIN 12
#define HID 64
#define NG 256            // 4 * LSTM_H gates
#define SPAD 68           // padded row stride for smem weight rows

// ---------------- scratch (device globals; no allocations allowed) ----------
__device__ int   g_deg[NN];
__device__ int   g_offs[NN];      // inclusive prefix of deg
__device__ int   g_cursor[NN];
__device__ float g_dinv[NN];
__device__ int   g_csrc[EE];
__device__ float g_ccoef[EE];
__device__ float g_feat[NN * HID];
__device__ float g_hw[NN * HID];
__device__ float g_xp[NN * NG];   // layer-0 LSTM input projection
__device__ int   g_bsum[256];

// ---------------- graph preprocessing ---------------------------------------
__global__ void k_zero_deg() {
    int i = blockIdx.x * 256 + threadIdx.x;
    if (i < NN) g_deg[i] = 0;
}

__global__ void k_count(const int* __restrict__ ei) {
    int e = blockIdx.x * 256 + threadIdx.x;
    if (e < EE) atomicAdd(&g_deg[ei[EE + e]], 1);
}

__global__ void k_dinv() {
    int i = blockIdx.x * 256 + threadIdx.x;
    if (i < NN) g_dinv[i] = rsqrtf((float)g_deg[i] + 1.0f);
}

__global__ void k_scanA() {
    __shared__ int s[256];
    int tid = threadIdx.x;
    int i = blockIdx.x * 256 + tid;
    int v = (i < NN) ? g_deg[i] : 0;
    s[tid] = v;
    __syncthreads();
    for (int o = 1; o < 256; o <<= 1) {
        int t = (tid >= o) ? s[tid - o] : 0;
        __syncthreads();
        s[tid] += t;
        __syncthreads();
    }
    if (i < NN) g_offs[i] = s[tid];
    if (tid == 255) g_bsum[blockIdx.x] = s[255];
}

__global__ void k_scanB() {
    __shared__ int s[256];
    int tid = threadIdx.x;
    int v = (tid < 188) ? g_bsum[tid] : 0;
    s[tid] = v;
    __syncthreads();
    for (int o = 1; o < 256; o <<= 1) {
        int t = (tid >= o) ? s[tid - o] : 0;
        __syncthreads();
        s[tid] += t;
        __syncthreads();
    }
    g_bsum[tid] = s[tid] - v;   // exclusive block prefix
}

__global__ void k_scanC() {
    int i = blockIdx.x * 256 + threadIdx.x;
    if (i < NN) {
        int o = g_offs[i] + g_bsum[blockIdx.x];
        g_offs[i] = o;
        g_cursor[i] = o - g_deg[i];
    }
}

__global__ void k_fill(const int* __restrict__ ei) {
    int e = blockIdx.x * 256 + threadIdx.x;
    if (e < EE) {
        int s = ei[e];
        int d = ei[EE + e];
        int p = atomicAdd(&g_cursor[d], 1);
        g_csrc[p] = s;
        g_ccoef[p] = g_dinv[s] * g_dinv[d];
    }
}

// ---------------- GCN matmuls ------------------------------------------------
__global__ void k_mm_in(const float* __restrict__ x, const float* __restrict__ W) {
    int idx = blockIdx.x * 256 + threadIdx.x;
    if (idx >= NN * HID) return;
    int n = idx >> 6, c = idx & 63;
    float acc = 0.f;
#pragma unroll
    for (int k = 0; k < FIN; k++) acc += x[n * FIN + k] * W[k * HID + c];
    g_hw[idx] = acc;
}

// g_hw = g_feat @ W  (64x64), 16 nodes per block
__global__ void k_mm64(const float* __restrict__ W) {
    __shared__ float sW[4096];
    __shared__ float sA[1024];
    int tid = threadIdx.x;
    int n0 = blockIdx.x * 16;
    for (int i = tid; i < 4096; i += 256) sW[i] = W[i];
    for (int i = tid; i < 1024; i += 256) sA[i] = g_feat[n0 * 64 + i];
    __syncthreads();
    int c4 = (tid & 15) * 4;
    int m = tid >> 4;
    float4 acc = make_float4(0.f, 0.f, 0.f, 0.f);
#pragma unroll
    for (int k4 = 0; k4 < 16; k4++) {
        float4 a4 = *(float4*)&sA[m * 64 + k4 * 4];
        float4 w;
        w = *(float4*)&sW[(k4 * 4 + 0) * 64 + c4];
        acc.x += a4.x * w.x; acc.y += a4.x * w.y; acc.z += a4.x * w.z; acc.w += a4.x * w.w;
        w = *(float4*)&sW[(k4 * 4 + 1) * 64 + c4];
        acc.x += a4.y * w.x; acc.y += a4.y * w.y; acc.z += a4.y * w.z; acc.w += a4.y * w.w;
        w = *(float4*)&sW[(k4 * 4 + 2) * 64 + c4];
        acc.x += a4.z * w.x; acc.y += a4.z * w.y; acc.z += a4.z * w.z; acc.w += a4.z * w.w;
        w = *(float4*)&sW[(k4 * 4 + 3) * 64 + c4];
        acc.x += a4.w * w.x; acc.y += a4.w * w.y; acc.z += a4.w * w.z; acc.w += a4.w * w.w;
    }
    *(float4*)&g_hw[(n0 + m) * 64 + c4] = acc;
}

// ---------------- GCN aggregation (gather CSR) + self + bias + relu ----------
__global__ void k_agg(const float* __restrict__ b) {
    int gw = (blockIdx.x * 256 + threadIdx.x) >> 5;
    int lane = threadIdx.x & 31;
    if (gw >= NN) return;
    int d = gw;
    int end = g_offs[d];
    int start = end - g_deg[d];
    float ax = 0.f, ay = 0.f;
    int e = start;
    for (; e + 2 <= end; e += 2) {
        int s0 = g_csrc[e], s1 = g_csrc[e + 1];
        float c0 = g_ccoef[e], c1 = g_ccoef[e + 1];
        float2 v0 = *(const float2*)&g_hw[s0 * 64 + lane * 2];
        float2 v1 = *(const float2*)&g_hw[s1 * 64 + lane * 2];
        ax += c0 * v0.x + c1 * v1.x;
        ay += c0 * v0.y + c1 * v1.y;
    }
    if (e < end) {
        int s0 = g_csrc[e];
        float c0 = g_ccoef[e];
        float2 v0 = *(const float2*)&g_hw[s0 * 64 + lane * 2];
        ax += c0 * v0.x;
        ay += c0 * v0.y;
    }
    float di = g_dinv[d];
    float dd = di * di;
    float2 sv = *(const float2*)&g_hw[d * 64 + lane * 2];
    float bx = b[lane * 2], by = b[lane * 2 + 1];
    float2 r;
    r.x = fmaxf(ax + sv.x * dd + bx, 0.f);
    r.y = fmaxf(ay + sv.y * dd + by, 0.f);
    *(float2*)&g_feat[d * 64 + lane * 2] = r;
}

// ---------------- LSTM layer-0 input projection ------------------------------
__global__ void k_xproj(const float* __restrict__ Wih,
                        const float* __restrict__ bih,
                        const float* __restrict__ bhh) {
    extern __shared__ float sm[];
    float* sW = sm;               // NG * SPAD
    float* sX = sm + NG * SPAD;   // 64
    float* sB = sX + 64;          // 256
    int tid = threadIdx.x;
    for (int i = tid; i < NG * HID; i += 256)
        sW[(i >> 6) * SPAD + (i & 63)] = Wih[i];
    sB[tid] = bih[tid] + bhh[tid];
    __syncthreads();
    for (int r = blockIdx.x; r < NN; r += gridDim.x) {
        if (tid < 16) *(float4*)&sX[tid * 4] = *(const float4*)&g_feat[r * 64 + tid * 4];
        __syncthreads();
        float acc = sB[tid];
#pragma unroll
        for (int j4 = 0; j4 < 16; j4++) {
            float4 x4 = *(float4*)&sX[j4 * 4];
            float4 w4 = *(float4*)&sW[tid * SPAD + j4 * 4];
            acc += x4.x * w4.x + x4.y * w4.y + x4.z * w4.z + x4.w * w4.w;
        }
        g_xp[r * NG + tid] = acc;
        __syncthreads();
    }
}

// ---------------- fused 2-layer LSTM + output projection ---------------------
__device__ __forceinline__ float sigf(float x) { return 1.f / (1.f + __expf(-x)); }
__device__ __forceinline__ float tanhfast(float x) { return 1.f - 2.f / (__expf(2.f * x) + 1.f); }

__global__ void __launch_bounds__(256, 1) k_lstm(
    const float* __restrict__ Whh0,
    const float* __restrict__ Wih1, const float* __restrict__ Whh1,
    const float* __restrict__ bih1, const float* __restrict__ bhh1,
    const float* __restrict__ Wout, const float* __restrict__ bout,
    float* __restrict__ out)
{
    extern __shared__ float sm[];
    float* sW0  = sm;                 // Whh0   NG*SPAD
    float* sWi1 = sm + NG * SPAD;     // Wih1
    float* sW1  = sm + 2 * NG * SPAD; // Whh1
    float* sh0  = sm + 3 * NG * SPAD; // 64
    float* sh1  = sh0 + 64;           // 64
    float* sg   = sh1 + 64;           // 256 (shared gate buffer, reused)
    float* sB1  = sg + 256;           // 256

    int tid = threadIdx.x;
    for (int i = tid; i < NG * HID; i += 256) {
        int r = (i >> 6) * SPAD + (i & 63);
        sW0[r]  = Whh0[i];
        sWi1[r] = Wih1[i];
        sW1[r]  = Whh1[i];
    }
    sB1[tid] = bih1[tid] + bhh1[tid];
    int gtype = tid >> 6;   // 0:i 1:f 2:g 3:o
    __syncthreads();

    for (int n = blockIdx.x; n < NODES; n += gridDim.x) {
        if (tid < 64) { sh0[tid] = 0.f; sh1[tid] = 0.f; }
        float c0 = 0.f, c1 = 0.f;
        __syncthreads();
        for (int t = 0; t < WIN; t++) {
            // layer 0 gates
            float a = g_xp[(t * NODES + n) * NG + tid];
#pragma unroll
            for (int j4 = 0; j4 < 16; j4++) {
                float4 h4 = *(float4*)&sh0[j4 * 4];
                float4 w4 = *(float4*)&sW0[tid * SPAD + j4 * 4];
                a += h4.x * w4.x + h4.y * w4.y + h4.z * w4.z + h4.w * w4.w;
            }
            sg[tid] = (gtype == 2) ? tanhfast(a) : sigf(a);
            __syncthreads();
            if (tid < 64) {
                float gi = sg[tid], gf = sg[64 + tid], gg = sg[128 + tid], go = sg[192 + tid];
                c0 = gf * c0 + gi * gg;
                sh0[tid] = go * tanhfast(c0);
            }
            __syncthreads();
            // layer 1 gates (input = new h0)
            float a1 = sB1[tid];
#pragma unroll
            for (int j4 = 0; j4 < 16; j4++) {
                float4 h4 = *(float4*)&sh0[j4 * 4];
                float4 w4 = *(float4*)&sWi1[tid * SPAD + j4 * 4];
                a1 += h4.x * w4.x + h4.y * w4.y + h4.z * w4.z + h4.w * w4.w;
                float4 g4 = *(float4*)&sh1[j4 * 4];
                float4 v4 = *(float4*)&sW1[tid * SPAD + j4 * 4];
                a1 += g4.x * v4.x + g4.y * v4.y + g4.z * v4.z + g4.w * v4.w;
            }
            sg[tid] = (gtype == 2) ? tanhfast(a1) : sigf(a1);
            __syncthreads();
            if (tid < 64) {
                float gi = sg[tid], gf = sg[64 + tid], gg = sg[128 + tid], go = sg[192 + tid];
                c1 = gf * c1 + gi * gg;
                sh1[tid] = go * tanhfast(c1);
            }
            __syncthreads();
        }
        // output projection: pred[n] = h1_last @ Wout + bout  (flat layout matches)
        if (tid < 96) {
            float acc = bout[tid];
#pragma unroll
            for (int k = 0; k < 64; k++) acc += sh1[k] * Wout[k * 96 + tid];
            out[n * 96 + tid] = acc;
        }
        __syncthreads();
    }
}

// ---------------- launcher ---------------------------------------------------
extern "C" void kernel_launch(void* const* d_in, const int* in_sizes, int n_in,
                              void* d_out, int out_size) {
    const float* x    = (const float*)d_in[0];
    const int*   ei   = (const int*)  d_in[1];
    const float* W1   = (const float*)d_in[2];
    const float* b1   = (const float*)d_in[3];
    const float* W2   = (const float*)d_in[4];
    const float* b2   = (const float*)d_in[5];
    const float* W3   = (const float*)d_in[6];
    const float* b3   = (const float*)d_in[7];
    const float* W4   = (const float*)d_in[8];
    const float* b4   = (const float*)d_in[9];
    const float* Wih0 = (const float*)d_in[10];
    const float* Whh0 = (const float*)d_in[11];
    const float* bih0 = (const float*)d_in[12];
    const float* bhh0 = (const float*)d_in[13];
    const float* Wih1 = (const float*)d_in[14];
    const float* Whh1 = (const float*)d_in[15];
    const float* bih1 = (const float*)d_in[16];
    const float* bhh1 = (const float*)d_in[17];
    const float* Wout = (const float*)d_in[18];
    const float* bout = (const float*)d_in[19];
    float* out = (float*)d_out;

    const int XPROJ_SMEM = (NG * SPAD + 64 + 256) * 4;             // 70912 B
    const int LSTM_SMEM  = (3 * NG * SPAD + 64 + 64 + 256 + 256) * 4; // 211456 B
    cudaFuncSetAttribute(k_xproj, cudaFuncAttributeMaxDynamicSharedMemorySize, XPROJ_SMEM);
    cudaFuncSetAttribute(k_lstm,  cudaFuncAttributeMaxDynamicSharedMemorySize, LSTM_SMEM);

    // graph preprocessing (per call; deterministic up to fp-sum order)
    k_zero_deg<<<188, 256>>>();
    k_count<<<3000, 256>>>(ei);
    k_dinv<<<188, 256>>>();
    k_scanA<<<188, 256>>>();
    k_scanB<<<1, 256>>>();
    k_scanC<<<188, 256>>>();
    k_fill<<<3000, 256>>>(ei);

    // GCN stack
    k_mm_in<<<12000, 256>>>(x, W1);
    k_agg<<<6000, 256>>>(b1);
    k_mm64<<<3000, 256>>>(W2);
    k_agg<<<6000, 256>>>(b2);
    k_mm64<<<3000, 256>>>(W3);
    k_agg<<<6000, 256>>>(b3);
    k_mm64<<<3000, 256>>>(W4);
    k_agg<<<6000, 256>>>(b4);

    // LSTM
    k_xproj<<<444, 256, XPROJ_SMEM>>>(Wih0, bih0, bhh0);
    k_lstm<<<148, 256, LSTM_SMEM>>>(Whh0, Wih1, Whh1, bih1, bhh1, Wout, bout, out);
}

// round 2
// speedup vs baseline: 1.6395x; 1.6395x over previous
#include <cuda_runtime.h>

#define NN 48000          // NUM_NODES * WINDOW
#define NODES 2000
#define WIN 24
#define EE 768000
#define FIN 12
#define HID 64
#define NG 256            // 4 * LSTM_H gates
#define SPAD 68           // padded row stride (conflict-free float4 with 256 rows)
#define NB 8              // nodes per block in fused LSTM

typedef unsigned long long u64t;

// ---------------- packed f32x2 helpers (Blackwell) ---------------------------
__device__ __forceinline__ void ffma2(u64t &d, u64t a, u64t b) {
    asm("fma.rn.f32x2 %0, %1, %2, %0;" : "+l"(d) : "l"(a), "l"(b));
}
__device__ __forceinline__ u64t add2(u64t a, u64t b) {
    u64t r; asm("add.rn.f32x2 %0, %1, %2;" : "=l"(r) : "l"(a), "l"(b)); return r;
}
__device__ __forceinline__ u64t pack2(float lo, float hi) {
    u64t r; asm("mov.b64 %0, {%1, %2};" : "=l"(r) : "f"(lo), "f"(hi)); return r;
}
__device__ __forceinline__ float hsum2(u64t v) {
    float lo, hi; asm("mov.b64 {%0, %1}, %2;" : "=f"(lo), "=f"(hi) : "l"(v));
    return lo + hi;
}
__device__ __forceinline__ float2 unpack2(u64t v) {
    float lo, hi; asm("mov.b64 {%0, %1}, %2;" : "=f"(lo), "=f"(hi) : "l"(v));
    return make_float2(lo, hi);
}

// ---------------- scratch (device globals; no allocations allowed) ----------
__device__ int   g_deg[NN];
__device__ int   g_offs[NN];
__device__ int   g_cursor[NN];
__device__ float g_dinv[NN];
__device__ int   g_csrc[EE];
__device__ __align__(16) float g_xs[NN * FIN];    // dinv-scaled input
__device__ __align__(16) float g_u12[NN * FIN];   // layer-1 aggregated (pre-W)
__device__ __align__(16) float g_feat[NN * HID];  // dinv-scaled activations
__device__ __align__(16) float g_hw[NN * HID];    // aggregated (pre-W)
__device__ __align__(16) float g_xp[NN * NG];     // LSTM-0 input projection
__device__ int   g_bsum[256];

// ---------------- graph preprocessing ---------------------------------------
__global__ void k_zero_deg() {
    int i = blockIdx.x * 256 + threadIdx.x;
    if (i < NN) g_deg[i] = 0;
}
__global__ void k_count(const int* __restrict__ ei) {
    int e = blockIdx.x * 256 + threadIdx.x;
    if (e < EE) atomicAdd(&g_deg[ei[EE + e]], 1);
}
__global__ void k_dinv() {
    int i = blockIdx.x * 256 + threadIdx.x;
    if (i < NN) g_dinv[i] = rsqrtf((float)g_deg[i] + 1.0f);
}
__global__ void k_scanA() {
    __shared__ int s[256];
    int tid = threadIdx.x;
    int i = blockIdx.x * 256 + tid;
    int v = (i < NN) ? g_deg[i] : 0;
    s[tid] = v;
    __syncthreads();
    for (int o = 1; o < 256; o <<= 1) {
        int t = (tid >= o) ? s[tid - o] : 0;
        __syncthreads();
        s[tid] += t;
        __syncthreads();
    }
    if (i < NN) g_offs[i] = s[tid];
    if (tid == 255) g_bsum[blockIdx.x] = s[255];
}
__global__ void k_scanB() {
    __shared__ int s[256];
    int tid = threadIdx.x;
    int v = (tid < 188) ? g_bsum[tid] : 0;
    s[tid] = v;
    __syncthreads();
    for (int o = 1; o < 256; o <<= 1) {
        int t = (tid >= o) ? s[tid - o] : 0;
        __syncthreads();
        s[tid] += t;
        __syncthreads();
    }
    g_bsum[tid] = s[tid] - v;
}
__global__ void k_scanC() {
    int i = blockIdx.x * 256 + threadIdx.x;
    if (i < NN) {
        int o = g_offs[i] + g_bsum[blockIdx.x];
        g_offs[i] = o;
        g_cursor[i] = o - g_deg[i];
    }
}
__global__ void k_fill(const int* __restrict__ ei) {
    int e = blockIdx.x * 256 + threadIdx.x;
    if (e < EE) {
        int s = ei[e];
        int d = ei[EE + e];
        int p = atomicAdd(&g_cursor[d], 1);
        g_csrc[p] = s;
    }
}

// ---------------- layer 1: scale x, aggregate 12-wide, 12->64 GEMM ----------
__global__ void k_scale_x(const float* __restrict__ x) {
    int i = blockIdx.x * 256 + threadIdx.x;
    if (i < NN * FIN) g_xs[i] = x[i] * g_dinv[i / FIN];
}

// warp handles 2 dst nodes (16 lanes each, 12 active)
__global__ void k_agg12() {
    int w = (blockIdx.x * 256 + threadIdx.x) >> 5;
    int lane = threadIdx.x & 31;
    int sub = lane >> 4, f = lane & 15;
    int d = w * 2 + sub;
    if (d >= NN || f >= FIN) return;
    int end = g_offs[d];
    int start = end - g_deg[d];
    float acc = 0.f;
    int e = start;
    for (; e + 2 <= end; e += 2) {
        int s0 = g_csrc[e], s1 = g_csrc[e + 1];
        acc += g_xs[s0 * FIN + f] + g_xs[s1 * FIN + f];
    }
    if (e < end) acc += g_xs[g_csrc[e] * FIN + f];
    acc += g_xs[d * FIN + f];
    g_u12[d * FIN + f] = g_dinv[d] * acc;
}

__global__ void k_mmA(const float* __restrict__ W1, const float* __restrict__ b1) {
    int idx = blockIdx.x * 256 + threadIdx.x;
    if (idx >= NN * HID) return;
    int n = idx >> 6, c = idx & 63;
    float acc = b1[c];
#pragma unroll
    for (int k = 0; k < FIN; k++) acc += g_u12[n * FIN + k] * W1[k * HID + c];
    g_feat[idx] = fmaxf(acc, 0.f) * g_dinv[n];
}

// ---------------- aggregate 64-wide: u = dinv * (sum hs_src + hs_self) ------
__global__ void k_agg64() {
    int d = (blockIdx.x * 256 + threadIdx.x) >> 5;
    if (d >= NN) return;
    int lane = threadIdx.x & 31;
    int end = g_offs[d];
    int start = end - g_deg[d];
    u64t acc = 0ULL;
    int e = start;
    for (; e + 4 <= end; e += 4) {
        int s0 = g_csrc[e], s1 = g_csrc[e + 1], s2 = g_csrc[e + 2], s3 = g_csrc[e + 3];
        u64t v0 = *(const u64t*)&g_feat[s0 * 64 + lane * 2];
        u64t v1 = *(const u64t*)&g_feat[s1 * 64 + lane * 2];
        u64t v2 = *(const u64t*)&g_feat[s2 * 64 + lane * 2];
        u64t v3 = *(const u64t*)&g_feat[s3 * 64 + lane * 2];
        acc = add2(acc, add2(add2(v0, v1), add2(v2, v3)));
    }
    for (; e < end; e++) {
        u64t v = *(const u64t*)&g_feat[g_csrc[e] * 64 + lane * 2];
        acc = add2(acc, v);
    }
    acc = add2(acc, *(const u64t*)&g_feat[d * 64 + lane * 2]);
    float2 r = unpack2(acc);
    float di = g_dinv[d];
    float2 o = make_float2(di * r.x, di * r.y);
    *(float2*)&g_hw[d * 64 + lane * 2] = o;
}

// ---------------- 64x64 GEMM + bias + relu (+dinv scale) --------------------
template <bool SCALE>
__global__ void k_mm64(const float* __restrict__ W, const float* __restrict__ b) {
    __shared__ float sW[4096];
    __shared__ float sA[1024];
    int tid = threadIdx.x;
    int n0 = blockIdx.x * 16;
    for (int i = tid; i < 4096; i += 256) sW[i] = W[i];
    for (int i = tid; i < 1024; i += 256) sA[i] = g_hw[n0 * 64 + i];
    __syncthreads();
    int c4 = (tid & 15) * 4;
    int m = tid >> 4;
    float4 acc = make_float4(b[c4], b[c4 + 1], b[c4 + 2], b[c4 + 3]);
#pragma unroll
    for (int k4 = 0; k4 < 16; k4++) {
        float4 a4 = *(float4*)&sA[m * 64 + k4 * 4];
        float4 w;
        w = *(float4*)&sW[(k4 * 4 + 0) * 64 + c4];
        acc.x += a4.x * w.x; acc.y += a4.x * w.y; acc.z += a4.x * w.z; acc.w += a4.x * w.w;
        w = *(float4*)&sW[(k4 * 4 + 1) * 64 + c4];
        acc.x += a4.y * w.x; acc.y += a4.y * w.y; acc.z += a4.y * w.z; acc.w += a4.y * w.w;
        w = *(float4*)&sW[(k4 * 4 + 2) * 64 + c4];
        acc.x += a4.z * w.x; acc.y += a4.z * w.y; acc.z += a4.z * w.z; acc.w += a4.z * w.w;
        w = *(float4*)&sW[(k4 * 4 + 3) * 64 + c4];
        acc.x += a4.w * w.x; acc.y += a4.w * w.y; acc.z += a4.w * w.z; acc.w += a4.w * w.w;
    }
    float s = SCALE ? g_dinv[n0 + m] : 1.f;
    float4 r;
    r.x = fmaxf(acc.x, 0.f) * s;
    r.y = fmaxf(acc.y, 0.f) * s;
    r.z = fmaxf(acc.z, 0.f) * s;
    r.w = fmaxf(acc.w, 0.f) * s;
    *(float4*)&g_feat[(n0 + m) * 64 + c4] = r;
}

// ---------------- LSTM layer-0 input projection (16-row tiles, f32x2) -------
__global__ void __launch_bounds__(256) k_xproj(const float* __restrict__ Wih,
                                               const float* __restrict__ bih,
                                               const float* __restrict__ bhh) {
    extern __shared__ float sm[];
    float* sW = sm;                 // NG * SPAD
    float* sX = sm + NG * SPAD;     // 16 * 64
    float* sB = sX + 16 * 64;       // 256
    int tid = threadIdx.x;
    for (int i = tid; i < NG * HID; i += 256)
        sW[(i >> 6) * SPAD + (i & 63)] = Wih[i];
    sB[tid] = bih[tid] + bhh[tid];
    __syncthreads();
    u64t binit = pack2(sB[tid], 0.f);

    for (int g0 = blockIdx.x * 16; g0 < NN; g0 += gridDim.x * 16) {
        *(float4*)&sX[tid * 4] = *(const float4*)&g_feat[g0 * 64 + tid * 4];
        __syncthreads();
        u64t acc[16];
#pragma unroll
        for (int r = 0; r < 16; r++) acc[r] = binit;
#pragma unroll
        for (int j4 = 0; j4 < 16; j4++) {
            ulonglong2 w = *(const ulonglong2*)&sW[tid * SPAD + j4 * 4];
#pragma unroll
            for (int r = 0; r < 16; r++) {
                ulonglong2 xv = *(const ulonglong2*)&sX[r * 64 + j4 * 4];
                ffma2(acc[r], w.x, xv.x);
                ffma2(acc[r], w.y, xv.y);
            }
        }
#pragma unroll
        for (int r = 0; r < 16; r++)
            g_xp[(g0 + r) * NG + tid] = hsum2(acc[r]);
        __syncthreads();
    }
}

// ---------------- fused 2-layer LSTM + output projection (NB nodes/block) ---
__device__ __forceinline__ float sigf(float x) { return 1.f / (1.f + __expf(-x)); }
__device__ __forceinline__ float tanhfast(float x) { return 1.f - 2.f / (__expf(2.f * x) + 1.f); }

__global__ void __launch_bounds__(256, 1) k_lstm(
    const float* __restrict__ Whh0,
    const float* __restrict__ Wih1, const float* __restrict__ Whh1,
    const float* __restrict__ bih1, const float* __restrict__ bhh1,
    const float* __restrict__ Wout, const float* __restrict__ bout,
    float* __restrict__ out)
{
    extern __shared__ float sm[];
    float* sW0  = sm;                  // Whh0   NG*SPAD
    float* sWi1 = sm + NG * SPAD;      // Wih1
    float* sW1  = sm + 2 * NG * SPAD;  // Whh1
    float* sh0  = sm + 3 * NG * SPAD;  // NB*64
    float* sh1  = sh0 + NB * 64;       // NB*64
    float* sg   = sh1 + NB * 64;       // NB*256
    float* sB1  = sg + NB * 256;       // 256

    int tid = threadIdx.x;
    for (int i = tid; i < NG * HID; i += 256) {
        int r = (i >> 6) * SPAD + (i & 63);
        sW0[r]  = Whh0[i];
        sWi1[r] = Wih1[i];
        sW1[r]  = Whh1[i];
    }
    sB1[tid] = bih1[tid] + bhh1[tid];
    int gtype = tid >> 6;   // 0:i 1:f 2:g 3:o
    __syncthreads();
    u64t b1p = pack2(sB1[tid], 0.f);

    for (int grp = blockIdx.x; grp < NODES / NB; grp += gridDim.x) {
        int n0 = grp * NB;
        sh0[tid] = 0.f; sh0[tid + 256] = 0.f;
        sh1[tid] = 0.f; sh1[tid + 256] = 0.f;
        float c0a = 0.f, c0b = 0.f, c1a = 0.f, c1b = 0.f;
        __syncthreads();

        for (int t = 0; t < WIN; t++) {
            // ---- layer 0 gates ----
            u64t acc[NB];
#pragma unroll
            for (int nn = 0; nn < NB; nn++)
                acc[nn] = pack2(g_xp[(t * NODES + n0 + nn) * NG + tid], 0.f);
#pragma unroll
            for (int j4 = 0; j4 < 16; j4++) {
                ulonglong2 w = *(const ulonglong2*)&sW0[tid * SPAD + j4 * 4];
#pragma unroll
                for (int nn = 0; nn < NB; nn++) {
                    ulonglong2 h = *(const ulonglong2*)&sh0[nn * 64 + j4 * 4];
                    ffma2(acc[nn], w.x, h.x);
                    ffma2(acc[nn], w.y, h.y);
                }
            }
#pragma unroll
            for (int nn = 0; nn < NB; nn++) {
                float v = hsum2(acc[nn]);
                sg[nn * 256 + tid] = (gtype == 2) ? tanhfast(v) : sigf(v);
            }
            __syncthreads();
            {
                int q = tid >> 6, e = tid & 63;
                float gi = sg[q * 256 + e],       gf = sg[q * 256 + 64 + e];
                float gg = sg[q * 256 + 128 + e], go = sg[q * 256 + 192 + e];
                c0a = gf * c0a + gi * gg;
                sh0[tid] = go * tanhfast(c0a);
                int i2 = tid + 256; q = i2 >> 6; e = i2 & 63;
                gi = sg[q * 256 + e];       gf = sg[q * 256 + 64 + e];
                gg = sg[q * 256 + 128 + e]; go = sg[q * 256 + 192 + e];
                c0b = gf * c0b + gi * gg;
                sh0[i2] = go * tanhfast(c0b);
            }
            __syncthreads();
            // ---- layer 1 gates ----
#pragma unroll
            for (int nn = 0; nn < NB; nn++) acc[nn] = b1p;
#pragma unroll
            for (int j4 = 0; j4 < 16; j4++) {
                ulonglong2 wi = *(const ulonglong2*)&sWi1[tid * SPAD + j4 * 4];
                ulonglong2 wh = *(const ulonglong2*)&sW1[tid * SPAD + j4 * 4];
#pragma unroll
                for (int nn = 0; nn < NB; nn++) {
                    ulonglong2 h0 = *(const ulonglong2*)&sh0[nn * 64 + j4 * 4];
                    ulonglong2 h1 = *(const ulonglong2*)&sh1[nn * 64 + j4 * 4];
                    ffma2(acc[nn], wi.x, h0.x);
                    ffma2(acc[nn], wi.y, h0.y);
                    ffma2(acc[nn], wh.x, h1.x);
                    ffma2(acc[nn], wh.y, h1.y);
                }
            }
#pragma unroll
            for (int nn = 0; nn < NB; nn++) {
                float v = hsum2(acc[nn]);
                sg[nn * 256 + tid] = (gtype == 2) ? tanhfast(v) : sigf(v);
            }
            __syncthreads();
            {
                int q = tid >> 6, e = tid & 63;
                float gi = sg[q * 256 + e],       gf = sg[q * 256 + 64 + e];
                float gg = sg[q * 256 + 128 + e], go = sg[q * 256 + 192 + e];
                c1a = gf * c1a + gi * gg;
                sh1[tid] = go * tanhfast(c1a);
                int i2 = tid + 256; q = i2 >> 6; e = i2 & 63;
                gi = sg[q * 256 + e];       gf = sg[q * 256 + 64 + e];
                gg = sg[q * 256 + 128 + e]; go = sg[q * 256 + 192 + e];
                c1b = gf * c1b + gi * gg;
                sh1[i2] = go * tanhfast(c1b);
            }
            __syncthreads();
        }
        // ---- output projection ----
        if (tid < 96) {
#pragma unroll
            for (int nn = 0; nn < NB; nn++) {
                float a = bout[tid];
#pragma unroll
                for (int k = 0; k < 64; k++)
                    a += sh1[nn * 64 + k] * Wout[k * 96 + tid];
                out[(n0 + nn) * 96 + tid] = a;
            }
        }
        __syncthreads();
    }
}

// ---------------- launcher ---------------------------------------------------
extern "C" void kernel_launch(void* const* d_in, const int* in_sizes, int n_in,
                              void* d_out, int out_size) {
    const float* x    = (const float*)d_in[0];
    const int*   ei   = (const int*)  d_in[1];
    const float* W1   = (const float*)d_in[2];
    const float* b1   = (const float*)d_in[3];
    const float* W2   = (const float*)d_in[4];
    const float* b2   = (const float*)d_in[5];
    const float* W3   = (const float*)d_in[6];
    const float* b3   = (const float*)d_in[7];
    const float* W4   = (const float*)d_in[8];
    const float* b4   = (const float*)d_in[9];
    const float* Wih0 = (const float*)d_in[10];
    const float* Whh0 = (const float*)d_in[11];
    const float* bih0 = (const float*)d_in[12];
    const float* bhh0 = (const float*)d_in[13];
    const float* Wih1 = (const float*)d_in[14];
    const float* Whh1 = (const float*)d_in[15];
    const float* bih1 = (const float*)d_in[16];
    const float* bhh1 = (const float*)d_in[17];
    const float* Wout = (const float*)d_in[18];
    const float* bout = (const float*)d_in[19];
    float* out = (float*)d_out;

    const int XPROJ_SMEM = (NG * SPAD + 16 * 64 + 256) * 4;
    const int LSTM_SMEM  = (3 * NG * SPAD + NB * 64 * 2 + NB * 256 + 256) * 4;
    cudaFuncSetAttribute(k_xproj, cudaFuncAttributeMaxDynamicSharedMemorySize, XPROJ_SMEM);
    cudaFuncSetAttribute(k_lstm,  cudaFuncAttributeMaxDynamicSharedMemorySize, LSTM_SMEM);

    // graph preprocessing
    k_zero_deg<<<188, 256>>>();
    k_count<<<3000, 256>>>(ei);
    k_dinv<<<188, 256>>>();
    k_scanA<<<188, 256>>>();
    k_scanB<<<1, 256>>>();
    k_scanC<<<188, 256>>>();
    k_fill<<<3000, 256>>>(ei);

    // GCN layer 1 (12-wide aggregation)
    k_scale_x<<<2250, 256>>>(x);
    k_agg12<<<3000, 256>>>();
    k_mmA<<<12000, 256>>>(W1, b1);

    // GCN layers 2-4 (64-wide)
    k_agg64<<<6000, 256>>>();
    k_mm64<true><<<3000, 256>>>(W2, b2);
    k_agg64<<<6000, 256>>>();
    k_mm64<true><<<3000, 256>>>(W3, b3);
    k_agg64<<<6000, 256>>>();
    k_mm64<false><<<3000, 256>>>(W4, b4);

    // LSTM
    k_xproj<<<296, 256, XPROJ_SMEM>>>(Wih0, bih0, bhh0);
    k_lstm<<<125, 256, LSTM_SMEM>>>(Whh0, Wih1, Whh1, bih1, bhh1, Wout, bout, out);
}

// round 4
// speedup vs baseline: 1.8099x; 1.1039x over previous
#include <cuda_runtime.h>

#define NN 48000          // NUM_NODES * WINDOW
#define NODES 2000
#define WIN 24
#define EE 768000
#define FIN 12
#define HID 64
#define NG 256            // 4 * LSTM_H gates
#define SPAD 68           // padded row stride for xproj weight smem
#define NB 14             // nodes per block in fused LSTM (143 blocks x 14 = 2002)
#define NBLK 143
#define NGRP 3000         // NN / 16

typedef unsigned long long u64t;

// ---------------- packed f32x2 helpers (Blackwell) ---------------------------
__device__ __forceinline__ void ffma2(u64t &d, u64t a, u64t b) {
    asm("fma.rn.f32x2 %0, %1, %2, %0;" : "+l"(d) : "l"(a), "l"(b));
}
__device__ __forceinline__ u64t add2(u64t a, u64t b) {
    u64t r; asm("add.rn.f32x2 %0, %1, %2;" : "=l"(r) : "l"(a), "l"(b)); return r;
}
__device__ __forceinline__ u64t pack2(float lo, float hi) {
    u64t r; asm("mov.b64 %0, {%1, %2};" : "=l"(r) : "f"(lo), "f"(hi)); return r;
}
__device__ __forceinline__ float hsum2(u64t v) {
    float lo, hi; asm("mov.b64 {%0, %1}, %2;" : "=f"(lo), "=f"(hi) : "l"(v));
    return lo + hi;
}
__device__ __forceinline__ float2 unpack2(u64t v) {
    float lo, hi; asm("mov.b64 {%0, %1}, %2;" : "=f"(lo), "=f"(hi) : "l"(v));
    return make_float2(lo, hi);
}

// ---------------- scratch (device globals) -----------------------------------
__device__ int   g_deg[NN];
__device__ int   g_offs[NN];
__device__ int   g_cursor[NN];
__device__ float g_dinv[NN];
__device__ int   g_csrc[EE];
__device__ __align__(16) float g_xs[NN * FIN];
__device__ __align__(16) float g_fA[NN * HID];
__device__ __align__(16) float g_fB[NN * HID];
__device__ __align__(16) float g_xp[NN * NG];
__device__ int   g_bsum[256];

// ---------------- graph preprocessing ---------------------------------------
__global__ void k_zero_deg() {
    int i = blockIdx.x * 256 + threadIdx.x;
    if (i < NN) g_deg[i] = 0;
}
__global__ void k_count(const int* __restrict__ ei) {
    int e = blockIdx.x * 256 + threadIdx.x;
    if (e < EE) atomicAdd(&g_deg[ei[EE + e]], 1);
}
__global__ void k_scanA() {
    __shared__ int s[256];
    int tid = threadIdx.x;
    int i = blockIdx.x * 256 + tid;
    int v = (i < NN) ? g_deg[i] : 0;
    s[tid] = v;
    __syncthreads();
    for (int o = 1; o < 256; o <<= 1) {
        int t = (tid >= o) ? s[tid - o] : 0;
        __syncthreads();
        s[tid] += t;
        __syncthreads();
    }
    if (i < NN) g_offs[i] = s[tid];
    if (tid == 255) g_bsum[blockIdx.x] = s[255];
}
__global__ void k_scanB() {
    __shared__ int s[256];
    int tid = threadIdx.x;
    int v = (tid < 188) ? g_bsum[tid] : 0;
    s[tid] = v;
    __syncthreads();
    for (int o = 1; o < 256; o <<= 1) {
        int t = (tid >= o) ? s[tid - o] : 0;
        __syncthreads();
        s[tid] += t;
        __syncthreads();
    }
    g_bsum[tid] = s[tid] - v;
}
// scanC fused with dinv computation + input scaling
__global__ void k_scanC(const float* __restrict__ x) {
    int i = blockIdx.x * 256 + threadIdx.x;
    if (i < NN) {
        int dg = g_deg[i];
        int o = g_offs[i] + g_bsum[blockIdx.x];
        g_offs[i] = o;
        g_cursor[i] = o - dg;
        float di = rsqrtf((float)dg + 1.0f);
        g_dinv[i] = di;
#pragma unroll
        for (int f = 0; f < FIN; f++) g_xs[i * FIN + f] = x[i * FIN + f] * di;
    }
}
__global__ void k_fill(const int* __restrict__ ei) {
    int e = blockIdx.x * 256 + threadIdx.x;
    if (e < EE) {
        int s = ei[e];
        int d = ei[EE + e];
        int p = atomicAdd(&g_cursor[d], 1);
        g_csrc[p] = s;
    }
}

// ---------------- layer 1: fused 12-wide aggregate + 12->64 GEMM -------------
__global__ void __launch_bounds__(256) k_layer1(const float* __restrict__ W1,
                                                const float* __restrict__ b1) {
    __shared__ float sW[FIN * 64];
    __shared__ float sb[64];
    __shared__ float sU[16 * FIN];
    int tid = threadIdx.x;
    int w = tid >> 5, lane = tid & 31;
    int sub = lane >> 4, f = lane & 15;
    for (int i = tid; i < FIN * 64; i += 256) sW[i] = W1[i];
    if (tid < 64) sb[tid] = b1[tid];
    __syncthreads();

#pragma unroll 1
    for (int grp = blockIdx.x; grp < NGRP; grp += gridDim.x) {
        int g0 = grp * 16;
        // gather: each warp handles 2 dsts via 16-lane halves
        {
            int m = w * 2 + sub;
            int d = g0 + m;
            if (f < FIN) {
                int end = g_offs[d];
                int start = end - g_deg[d];
                float acc = 0.f;
                int e = start;
                for (; e + 4 <= end; e += 4) {
                    int s0 = g_csrc[e], s1 = g_csrc[e + 1], s2 = g_csrc[e + 2], s3 = g_csrc[e + 3];
                    acc += g_xs[s0 * FIN + f] + g_xs[s1 * FIN + f]
                         + g_xs[s2 * FIN + f] + g_xs[s3 * FIN + f];
                }
                for (; e < end; e++) acc += g_xs[g_csrc[e] * FIN + f];
                acc += g_xs[d * FIN + f];
                sU[m * FIN + f] = g_dinv[d] * acc;
            }
        }
        __syncthreads();
        // GEMM 16x12 @ 12x64, relu, dinv-scale
        {
            int c4 = (tid & 15) * 4;
            int m = tid >> 4;
            float4 acc = make_float4(sb[c4], sb[c4 + 1], sb[c4 + 2], sb[c4 + 3]);
#pragma unroll
            for (int k = 0; k < FIN; k++) {
                float a = sU[m * FIN + k];
                float4 wv = *(float4*)&sW[k * 64 + c4];
                acc.x += a * wv.x; acc.y += a * wv.y; acc.z += a * wv.z; acc.w += a * wv.w;
            }
            float s = g_dinv[g0 + m];
            float4 r;
            r.x = fmaxf(acc.x, 0.f) * s;
            r.y = fmaxf(acc.y, 0.f) * s;
            r.z = fmaxf(acc.z, 0.f) * s;
            r.w = fmaxf(acc.w, 0.f) * s;
            *(float4*)&g_fA[(g0 + m) * 64 + c4] = r;
        }
        __syncthreads();
    }
}

// ---------------- fused 64-wide aggregate + 64x64 GEMM ----------------------
// SRCA: read g_fA else g_fB (write the other). SCALE: scale output by dinv.
template <bool SRCA, bool SCALE>
__global__ void __launch_bounds__(256) k_layer64(const float* __restrict__ W,
                                                 const float* __restrict__ b) {
    __shared__ float sW[4096];
    __shared__ float sb[64];
    __shared__ __align__(16) float sA[1024];
    const float* __restrict__ src = SRCA ? g_fA : g_fB;
    float* __restrict__ dst = SRCA ? g_fB : g_fA;
    int tid = threadIdx.x;
    int w = tid >> 5, lane = tid & 31;
    for (int i = tid; i < 4096; i += 256) sW[i] = W[i];
    if (tid < 64) sb[tid] = b[tid];
    __syncthreads();

#pragma unroll 1
    for (int grp = blockIdx.x; grp < NGRP; grp += gridDim.x) {
        int g0 = grp * 16;
        // gather: warp handles dsts w and w+8
#pragma unroll 1
        for (int pass = 0; pass < 2; pass++) {
            int m = w + pass * 8;
            int d = g0 + m;
            int end = g_offs[d];
            int start = end - g_deg[d];
            u64t acc = 0ULL;
            int e = start;
            for (; e + 8 <= end; e += 8) {
                int s0 = g_csrc[e],     s1 = g_csrc[e + 1], s2 = g_csrc[e + 2], s3 = g_csrc[e + 3];
                int s4 = g_csrc[e + 4], s5 = g_csrc[e + 5], s6 = g_csrc[e + 6], s7 = g_csrc[e + 7];
                u64t v0 = *(const u64t*)&src[s0 * 64 + lane * 2];
                u64t v1 = *(const u64t*)&src[s1 * 64 + lane * 2];
                u64t v2 = *(const u64t*)&src[s2 * 64 + lane * 2];
                u64t v3 = *(const u64t*)&src[s3 * 64 + lane * 2];
                u64t v4 = *(const u64t*)&src[s4 * 64 + lane * 2];
                u64t v5 = *(const u64t*)&src[s5 * 64 + lane * 2];
                u64t v6 = *(const u64t*)&src[s6 * 64 + lane * 2];
                u64t v7 = *(const u64t*)&src[s7 * 64 + lane * 2];
                acc = add2(acc, add2(add2(add2(v0, v1), add2(v2, v3)),
                                     add2(add2(v4, v5), add2(v6, v7))));
            }
            for (; e < end; e++) {
                u64t v = *(const u64t*)&src[g_csrc[e] * 64 + lane * 2];
                acc = add2(acc, v);
            }
            acc = add2(acc, *(const u64t*)&src[d * 64 + lane * 2]);
            float2 r = unpack2(acc);
            float di = g_dinv[d];
            sA[m * 64 + lane * 2] = di * r.x;
            sA[m * 64 + lane * 2 + 1] = di * r.y;
        }
        __syncthreads();
        // GEMM 16x64 @ 64x64 + bias + relu (+dinv)
        {
            int c4 = (tid & 15) * 4;
            int m = tid >> 4;
            float4 acc = make_float4(sb[c4], sb[c4 + 1], sb[c4 + 2], sb[c4 + 3]);
#pragma unroll
            for (int k4 = 0; k4 < 16; k4++) {
                float4 a4 = *(float4*)&sA[m * 64 + k4 * 4];
                float4 wv;
                wv = *(float4*)&sW[(k4 * 4 + 0) * 64 + c4];
                acc.x += a4.x * wv.x; acc.y += a4.x * wv.y; acc.z += a4.x * wv.z; acc.w += a4.x * wv.w;
                wv = *(float4*)&sW[(k4 * 4 + 1) * 64 + c4];
                acc.x += a4.y * wv.x; acc.y += a4.y * wv.y; acc.z += a4.y * wv.z; acc.w += a4.y * wv.w;
                wv = *(float4*)&sW[(k4 * 4 + 2) * 64 + c4];
                acc.x += a4.z * wv.x; acc.y += a4.z * wv.y; acc.z += a4.z * wv.z; acc.w += a4.z * wv.w;
                wv = *(float4*)&sW[(k4 * 4 + 3) * 64 + c4];
                acc.x += a4.w * wv.x; acc.y += a4.w * wv.y; acc.z += a4.w * wv.z; acc.w += a4.w * wv.w;
            }
            float s = SCALE ? g_dinv[g0 + m] : 1.f;
            float4 r;
            r.x = fmaxf(acc.x, 0.f) * s;
            r.y = fmaxf(acc.y, 0.f) * s;
            r.z = fmaxf(acc.z, 0.f) * s;
            r.w = fmaxf(acc.w, 0.f) * s;
            *(float4*)&dst[(g0 + m) * 64 + c4] = r;
        }
        __syncthreads();
    }
}

// ---------------- LSTM layer-0 input projection (16-row tiles, f32x2) -------
__global__ void __launch_bounds__(256) k_xproj(const float* __restrict__ Wih,
                                               const float* __restrict__ bih,
                                               const float* __restrict__ bhh) {
    extern __shared__ float sm[];
    float* sW = sm;                 // NG * SPAD
    float* sX = sm + NG * SPAD;     // 16 * 64
    float* sB = sX + 16 * 64;       // 256
    int tid = threadIdx.x;
    for (int i = tid; i < NG * HID; i += 256)
        sW[(i >> 6) * SPAD + (i & 63)] = Wih[i];
    sB[tid] = bih[tid] + bhh[tid];
    __syncthreads();
    u64t binit = pack2(sB[tid], 0.f);

#pragma unroll 1
    for (int g0 = blockIdx.x * 16; g0 < NN; g0 += gridDim.x * 16) {
        *(float4*)&sX[tid * 4] = *(const float4*)&g_fB[g0 * 64 + tid * 4];
        __syncthreads();
        u64t acc[16];
#pragma unroll
        for (int r = 0; r < 16; r++) acc[r] = binit;
#pragma unroll 8
        for (int j4 = 0; j4 < 16; j4++) {
            ulonglong2 wv = *(const ulonglong2*)&sW[tid * SPAD + j4 * 4];
#pragma unroll
            for (int r = 0; r < 16; r++) {
                ulonglong2 xv = *(const ulonglong2*)&sX[r * 64 + j4 * 4];
                ffma2(acc[r], wv.x, xv.x);
                ffma2(acc[r], wv.y, xv.y);
            }
        }
#pragma unroll
        for (int r = 0; r < 16; r++)
            g_xp[(g0 + r) * NG + tid] = hsum2(acc[r]);
        __syncthreads();
    }
}

// ---------------- fused 2-layer LSTM + output projection (NB=14/block) ------
__device__ __forceinline__ float sigf(float x) { return 1.f / (1.f + __expf(-x)); }
__device__ __forceinline__ float tanhfast(float x) { return 1.f - 2.f / (__expf(2.f * x) + 1.f); }

__global__ void __launch_bounds__(256, 1) k_lstm(
    const float* __restrict__ Whh0,
    const float* __restrict__ Wih1, const float* __restrict__ Whh1,
    const float* __restrict__ bih1, const float* __restrict__ bhh1,
    const float* __restrict__ Wout, const float* __restrict__ bout,
    float* __restrict__ out)
{
    extern __shared__ float sm[];
    float* sW0  = sm;                  // 16384
    float* sWi1 = sm + 16384;          // 16384
    float* sW1  = sm + 32768;          // 16384
    float* sh0  = sm + 49152;          // NB*64 = 896
    float* sh1  = sh0 + NB * 64;       // 896
    float* sg   = sh1 + NB * 64;       // NB*256 = 3584
    float* sB1  = sg + NB * 256;       // 256

    int tid = threadIdx.x;
    for (int i = tid; i < NG * HID; i += 256) {
        int r = i >> 6, c = i & 63;
        int pos = r * 64 + (((c >> 2) ^ (r & 15)) << 2) + (c & 3);
        sW0[pos]  = Whh0[i];
        sWi1[pos] = Wih1[i];
        sW1[pos]  = Whh1[i];
    }
    sB1[tid] = bih1[tid] + bhh1[tid];
    for (int i = tid; i < NB * 64; i += 256) { sh0[i] = 0.f; sh1[i] = 0.f; }
    int gtype = tid >> 6;   // 0:i 1:f 2:g 3:o
    int wbase = tid * 64;
    int wrot  = tid & 15;
    __syncthreads();
    u64t b1p = pack2(sB1[tid], 0.f);

    int n0 = blockIdx.x * NB;
    float c0[4] = {0.f, 0.f, 0.f, 0.f};
    float c1[4] = {0.f, 0.f, 0.f, 0.f};

#pragma unroll 1
    for (int t = 0; t < WIN; t++) {
        // ---- layer 0 gates ----
        u64t acc[NB];
#pragma unroll
        for (int nn = 0; nn < NB; nn++) {
            int n = n0 + nn;
            int nc = (n < NODES) ? n : (NODES - 1);
            acc[nn] = pack2(g_xp[(t * NODES + nc) * NG + tid], 0.f);
        }
#pragma unroll 8
        for (int j4 = 0; j4 < 16; j4++) {
            ulonglong2 wv = *(const ulonglong2*)&sW0[wbase + ((j4 ^ wrot) << 2)];
#pragma unroll
            for (int nn = 0; nn < NB; nn++) {
                ulonglong2 h = *(const ulonglong2*)&sh0[nn * 64 + j4 * 4];
                ffma2(acc[nn], wv.x, h.x);
                ffma2(acc[nn], wv.y, h.y);
            }
        }
#pragma unroll
        for (int nn = 0; nn < NB; nn++) {
            float v = hsum2(acc[nn]);
            sg[nn * 256 + tid] = (gtype == 2) ? tanhfast(v) : sigf(v);
        }
        __syncthreads();
#pragma unroll
        for (int r = 0; r < 4; r++) {
            int idx = tid + 256 * r;
            if (idx < NB * 64) {
                int nn = idx >> 6, e = idx & 63;
                float gi = sg[nn * 256 + e],       gf = sg[nn * 256 + 64 + e];
                float gg = sg[nn * 256 + 128 + e], go = sg[nn * 256 + 192 + e];
                c0[r] = gf * c0[r] + gi * gg;
                sh0[idx] = go * tanhfast(c0[r]);
            }
        }
        __syncthreads();
        // ---- layer 1 gates ----
#pragma unroll
        for (int nn = 0; nn < NB; nn++) acc[nn] = b1p;
#pragma unroll 8
        for (int j4 = 0; j4 < 16; j4++) {
            int wo = (j4 ^ wrot) << 2;
            ulonglong2 wi = *(const ulonglong2*)&sWi1[wbase + wo];
            ulonglong2 wh = *(const ulonglong2*)&sW1[wbase + wo];
#pragma unroll
            for (int nn = 0; nn < NB; nn++) {
                ulonglong2 h0 = *(const ulonglong2*)&sh0[nn * 64 + j4 * 4];
                ulonglong2 h1 = *(const ulonglong2*)&sh1[nn * 64 + j4 * 4];
                ffma2(acc[nn], wi.x, h0.x);
                ffma2(acc[nn], wi.y, h0.y);
                ffma2(acc[nn], wh.x, h1.x);
                ffma2(acc[nn], wh.y, h1.y);
            }
        }
#pragma unroll
        for (int nn = 0; nn < NB; nn++) {
            float v = hsum2(acc[nn]);
            sg[nn * 256 + tid] = (gtype == 2) ? tanhfast(v) : sigf(v);
        }
        __syncthreads();
#pragma unroll
        for (int r = 0; r < 4; r++) {
            int idx = tid + 256 * r;
            if (idx < NB * 64) {
                int nn = idx >> 6, e = idx & 63;
                float gi = sg[nn * 256 + e],       gf = sg[nn * 256 + 64 + e];
                float gg = sg[nn * 256 + 128 + e], go = sg[nn * 256 + 192 + e];
                c1[r] = gf * c1[r] + gi * gg;
                sh1[idx] = go * tanhfast(c1[r]);
            }
        }
        __syncthreads();
    }
    // ---- output projection: 14 nodes x 96 outputs ----
#pragma unroll 1
    for (int i = tid; i < NB * 96; i += 256) {
        int nn = i / 96, o = i - nn * 96;
        int n = n0 + nn;
        if (n < NODES) {
            float a = bout[o];
#pragma unroll
            for (int k = 0; k < 64; k++)
                a += sh1[nn * 64 + k] * Wout[k * 96 + o];
            out[n * 96 + o] = a;
        }
    }
}

// ---------------- launcher ---------------------------------------------------
extern "C" void kernel_launch(void* const* d_in, const int* in_sizes, int n_in,
                              void* d_out, int out_size) {
    const float* x    = (const float*)d_in[0];
    const int*   ei   = (const int*)  d_in[1];
    const float* W1   = (const float*)d_in[2];
    const float* b1   = (const float*)d_in[3];
    const float* W2   = (const float*)d_in[4];
    const float* b2   = (const float*)d_in[5];
    const float* W3   = (const float*)d_in[6];
    const float* b3   = (const float*)d_in[7];
    const float* W4   = (const float*)d_in[8];
    const float* b4   = (const float*)d_in[9];
    const float* Wih0 = (const float*)d_in[10];
    const float* Whh0 = (const float*)d_in[11];
    const float* bih0 = (const float*)d_in[12];
    const float* bhh0 = (const float*)d_in[13];
    const float* Wih1 = (const float*)d_in[14];
    const float* Whh1 = (const float*)d_in[15];
    const float* bih1 = (const float*)d_in[16];
    const float* bhh1 = (const float*)d_in[17];
    const float* Wout = (const float*)d_in[18];
    const float* bout = (const float*)d_in[19];
    float* out = (float*)d_out;

    const int XPROJ_SMEM = (NG * SPAD + 16 * 64 + 256) * 4;                   // 74752
    const int LSTM_SMEM  = (3 * 16384 + NB * 64 * 2 + NB * 256 + 256) * 4;    // 219136
    cudaFuncSetAttribute(k_xproj, cudaFuncAttributeMaxDynamicSharedMemorySize, XPROJ_SMEM);
    cudaFuncSetAttribute(k_lstm,  cudaFuncAttributeMaxDynamicSharedMemorySize, LSTM_SMEM);

    // graph preprocessing
    k_zero_deg<<<188, 256>>>();
    k_count<<<3000, 256>>>(ei);
    k_scanA<<<188, 256>>>();
    k_scanB<<<1, 256>>>();
    k_scanC<<<188, 256>>>(x);
    k_fill<<<3000, 256>>>(ei);

    // GCN stack (fused aggregate + GEMM, double-buffered A/B)
    k_layer1<<<750, 256>>>(W1, b1);                  // xs -> A
    k_layer64<true,  true ><<<750, 256>>>(W2, b2);   // A -> B
    k_layer64<false, true ><<<750, 256>>>(W3, b3);   // B -> A
    k_layer64<true,  false><<<750, 256>>>(W4, b4);   // A -> B (unscaled)

    // LSTM
    k_xproj<<<444, 256, XPROJ_SMEM>>>(Wih0, bih0, bhh0);
    k_lstm<<<NBLK, 256, LSTM_SMEM>>>(Whh0, Wih1, Whh1, bih1, bhh1, Wout, bout, out);
}

// round 8
// speedup vs baseline: 1.9081x; 1.0542x over previous
#include <cuda_runtime.h>

#define NN 48000          // NUM_NODES * WINDOW
#define NODES 2000
#define WIN 24
#define EE 768000
#define FIN 12
#define HID 64
#define NG 256            // 4 * LSTM_H gates
#define NB 14             // nodes per block in fused LSTM (143 blocks x 14 = 2002)
#define NBLK 143
#define NGRP1 3000        // NN / 16  (layer1 groups)
#define NGRP64 1500       // NN / 32  (layer64 groups)
#define NTILE 1500        // NN / 32  (xproj tiles, 32 rows each)

typedef unsigned long long u64t;

// ---------------- packed f32x2 helpers (Blackwell) ---------------------------
__device__ __forceinline__ void ffma2(u64t &d, u64t a, u64t b) {
    asm("fma.rn.f32x2 %0, %1, %2, %0;" : "+l"(d) : "l"(a), "l"(b));
}
__device__ __forceinline__ u64t add2(u64t a, u64t b) {
    u64t r; asm("add.rn.f32x2 %0, %1, %2;" : "=l"(r) : "l"(a), "l"(b)); return r;
}
__device__ __forceinline__ u64t pack2(float lo, float hi) {
    u64t r; asm("mov.b64 %0, {%1, %2};" : "=l"(r) : "f"(lo), "f"(hi)); return r;
}
__device__ __forceinline__ float hsum2(u64t v) {
    float lo, hi; asm("mov.b64 {%0, %1}, %2;" : "=f"(lo), "=f"(hi) : "l"(v));
    return lo + hi;
}
__device__ __forceinline__ float2 unpack2(u64t v) {
    float lo, hi; asm("mov.b64 {%0, %1}, %2;" : "=f"(lo), "=f"(hi) : "l"(v));
    return make_float2(lo, hi);
}

// ---------------- scratch (device globals) -----------------------------------
__device__ int   g_deg[NN];
__device__ int   g_offs[NN];
__device__ int   g_cursor[NN];
__device__ float g_dinv[NN];
__device__ int   g_csrc[EE];
__device__ __align__(16) float g_xs[NN * FIN];
__device__ __align__(16) float g_fA[NN * HID];
__device__ __align__(16) float g_fB[NN * HID];
__device__ __align__(16) float g_xp[NN * NG];
__device__ int   g_bsum[256];

// ---------------- graph preprocessing ---------------------------------------
__global__ void k_zero_deg() {
    int i = blockIdx.x * 256 + threadIdx.x;
    if (i < NN) g_deg[i] = 0;
}
__global__ void k_count(const int* __restrict__ ei) {
    int e = blockIdx.x * 256 + threadIdx.x;
    if (e < EE) atomicAdd(&g_deg[ei[EE + e]], 1);
}
__global__ void k_scanA() {
    __shared__ int s[256];
    int tid = threadIdx.x;
    int i = blockIdx.x * 256 + tid;
    int v = (i < NN) ? g_deg[i] : 0;
    s[tid] = v;
    __syncthreads();
    for (int o = 1; o < 256; o <<= 1) {
        int t = (tid >= o) ? s[tid - o] : 0;
        __syncthreads();
        s[tid] += t;
        __syncthreads();
    }
    if (i < NN) g_offs[i] = s[tid];
    if (tid == 255) g_bsum[blockIdx.x] = s[255];
}
// scanC: per-block base computed locally (scanB merged in) + dinv + x scaling
__global__ void k_scanC(const float* __restrict__ x) {
    __shared__ int s[256];
    int b = blockIdx.x, tid = threadIdx.x;
    int v = (tid < b) ? g_bsum[tid] : 0;   // b <= 187 < 256
    s[tid] = v;
    __syncthreads();
    for (int o = 128; o > 0; o >>= 1) {
        if (tid < o) s[tid] += s[tid + o];
        __syncthreads();
    }
    int base = s[0];
    int i = b * 256 + tid;
    if (i < NN) {
        int dg = g_deg[i];
        int o = g_offs[i] + base;
        g_offs[i] = o;
        g_cursor[i] = o - dg;
        float di = rsqrtf((float)dg + 1.0f);
        g_dinv[i] = di;
#pragma unroll
        for (int f = 0; f < FIN; f++) g_xs[i * FIN + f] = x[i * FIN + f] * di;
    }
}
__global__ void k_fill(const int* __restrict__ ei) {
    int e = blockIdx.x * 256 + threadIdx.x;
    if (e < EE) {
        int s = ei[e];
        int d = ei[EE + e];
        int p = atomicAdd(&g_cursor[d], 1);
        g_csrc[p] = s;
    }
}

// ---------------- layer 1: fused 12-wide aggregate + 12->64 GEMM -------------
__global__ void __launch_bounds__(256) k_layer1(const float* __restrict__ W1,
                                                const float* __restrict__ b1) {
    __shared__ float sW[FIN * 64];
    __shared__ float sb[64];
    __shared__ float sU[16 * FIN];
    int tid = threadIdx.x;
    int w = tid >> 5, lane = tid & 31;
    int sub = lane >> 4, f = lane & 15;
    for (int i = tid; i < FIN * 64; i += 256) sW[i] = W1[i];
    if (tid < 64) sb[tid] = b1[tid];
    __syncthreads();

#pragma unroll 1
    for (int grp = blockIdx.x; grp < NGRP1; grp += gridDim.x) {
        int g0 = grp * 16;
        {
            int m = w * 2 + sub;
            int d = g0 + m;
            if (f < FIN) {
                int end = g_offs[d];
                int start = end - g_deg[d];
                float acc = 0.f;
                int e = start;
                for (; e + 4 <= end; e += 4) {
                    int s0 = g_csrc[e], s1 = g_csrc[e + 1], s2 = g_csrc[e + 2], s3 = g_csrc[e + 3];
                    acc += g_xs[s0 * FIN + f] + g_xs[s1 * FIN + f]
                         + g_xs[s2 * FIN + f] + g_xs[s3 * FIN + f];
                }
                for (; e < end; e++) acc += g_xs[g_csrc[e] * FIN + f];
                acc += g_xs[d * FIN + f];
                sU[m * FIN + f] = g_dinv[d] * acc;
            }
        }
        __syncthreads();
        {
            int c4 = (tid & 15) * 4;
            int m = tid >> 4;
            float4 acc = make_float4(sb[c4], sb[c4 + 1], sb[c4 + 2], sb[c4 + 3]);
#pragma unroll
            for (int k = 0; k < FIN; k++) {
                float a = sU[m * FIN + k];
                float4 wv = *(float4*)&sW[k * 64 + c4];
                acc.x += a * wv.x; acc.y += a * wv.y; acc.z += a * wv.z; acc.w += a * wv.w;
            }
            float s = g_dinv[g0 + m];
            float4 r;
            r.x = fmaxf(acc.x, 0.f) * s;
            r.y = fmaxf(acc.y, 0.f) * s;
            r.z = fmaxf(acc.z, 0.f) * s;
            r.w = fmaxf(acc.w, 0.f) * s;
            *(float4*)&g_fA[(g0 + m) * 64 + c4] = r;
        }
        __syncthreads();
    }
}

// ---------------- fused 64-wide aggregate + 64x64 GEMM (32 dsts/grp) ---------
// SRCA: read g_fA else g_fB (write the other). SCALE: scale output by dinv.
template <bool SRCA, bool SCALE>
__global__ void __launch_bounds__(256) k_layer64(const float* __restrict__ W,
                                                 const float* __restrict__ b) {
    __shared__ float sW[4096];
    __shared__ float sb[64];
    __shared__ __align__(16) float sA[2048];
    const float* __restrict__ src = SRCA ? g_fA : g_fB;
    float* __restrict__ dst = SRCA ? g_fB : g_fA;
    int tid = threadIdx.x;
    int w = tid >> 5, lane = tid & 31;
    for (int i = tid; i < 4096; i += 256) sW[i] = W[i];
    if (tid < 64) sb[tid] = b[tid];
    __syncthreads();

#pragma unroll 1
    for (int grp = blockIdx.x; grp < NGRP64; grp += gridDim.x) {
        int g0 = grp * 32;
        // gather: each warp handles 4 dsts concurrently (high MLP)
        {
            int d[4]; int e[4], en[4]; u64t acc[4];
#pragma unroll
            for (int p = 0; p < 4; p++) {
                d[p] = g0 + w + p * 8;
                en[p] = g_offs[d[p]];
                e[p] = en[p] - g_deg[d[p]];
                acc[p] = 0ULL;
            }
            for (;;) {
                bool done = true;
#pragma unroll
                for (int p = 0; p < 4; p++) {
                    if (e[p] + 4 <= en[p]) {
                        done = false;
                        int s0 = g_csrc[e[p]],     s1 = g_csrc[e[p] + 1];
                        int s2 = g_csrc[e[p] + 2], s3 = g_csrc[e[p] + 3];
                        u64t v0 = *(const u64t*)&src[s0 * 64 + lane * 2];
                        u64t v1 = *(const u64t*)&src[s1 * 64 + lane * 2];
                        u64t v2 = *(const u64t*)&src[s2 * 64 + lane * 2];
                        u64t v3 = *(const u64t*)&src[s3 * 64 + lane * 2];
                        acc[p] = add2(acc[p], add2(add2(v0, v1), add2(v2, v3)));
                        e[p] += 4;
                    }
                }
                if (done) break;
            }
#pragma unroll
            for (int p = 0; p < 4; p++) {
                for (; e[p] < en[p]; e[p]++) {
                    u64t v = *(const u64t*)&src[g_csrc[e[p]] * 64 + lane * 2];
                    acc[p] = add2(acc[p], v);
                }
                acc[p] = add2(acc[p], *(const u64t*)&src[d[p] * 64 + lane * 2]);
                float2 r = unpack2(acc[p]);
                float di = g_dinv[d[p]];
                sA[(w + p * 8) * 64 + lane * 2]     = di * r.x;
                sA[(w + p * 8) * 64 + lane * 2 + 1] = di * r.y;
            }
        }
        __syncthreads();
        // GEMM 32x64 @ 64x64 + bias + relu (+dinv) — 8 outputs/thread
        {
            int c4 = (tid & 15) * 4;
            int m = tid >> 4;                  // rows m and m+16
            float4 acc0 = make_float4(sb[c4], sb[c4 + 1], sb[c4 + 2], sb[c4 + 3]);
            float4 acc1 = acc0;
#pragma unroll
            for (int k4 = 0; k4 < 16; k4++) {
                float4 a0 = *(float4*)&sA[m * 64 + k4 * 4];
                float4 a1 = *(float4*)&sA[(m + 16) * 64 + k4 * 4];
                float4 wv;
                wv = *(float4*)&sW[(k4 * 4 + 0) * 64 + c4];
                acc0.x += a0.x * wv.x; acc0.y += a0.x * wv.y; acc0.z += a0.x * wv.z; acc0.w += a0.x * wv.w;
                acc1.x += a1.x * wv.x; acc1.y += a1.x * wv.y; acc1.z += a1.x * wv.z; acc1.w += a1.x * wv.w;
                wv = *(float4*)&sW[(k4 * 4 + 1) * 64 + c4];
                acc0.x += a0.y * wv.x; acc0.y += a0.y * wv.y; acc0.z += a0.y * wv.z; acc0.w += a0.y * wv.w;
                acc1.x += a1.y * wv.x; acc1.y += a1.y * wv.y; acc1.z += a1.y * wv.z; acc1.w += a1.y * wv.w;
                wv = *(float4*)&sW[(k4 * 4 + 2) * 64 + c4];
                acc0.x += a0.z * wv.x; acc0.y += a0.z * wv.y; acc0.z += a0.z * wv.z; acc0.w += a0.z * wv.w;
                acc1.x += a1.z * wv.x; acc1.y += a1.z * wv.y; acc1.z += a1.z * wv.z; acc1.w += a1.z * wv.w;
                wv = *(float4*)&sW[(k4 * 4 + 3) * 64 + c4];
                acc0.x += a0.w * wv.x; acc0.y += a0.w * wv.y; acc0.z += a0.w * wv.z; acc0.w += a0.w * wv.w;
                acc1.x += a1.w * wv.x; acc1.y += a1.w * wv.y; acc1.z += a1.w * wv.z; acc1.w += a1.w * wv.w;
            }
            float s0 = SCALE ? g_dinv[g0 + m] : 1.f;
            float s1 = SCALE ? g_dinv[g0 + m + 16] : 1.f;
            float4 r0, r1;
            r0.x = fmaxf(acc0.x, 0.f) * s0; r0.y = fmaxf(acc0.y, 0.f) * s0;
            r0.z = fmaxf(acc0.z, 0.f) * s0; r0.w = fmaxf(acc0.w, 0.f) * s0;
            r1.x = fmaxf(acc1.x, 0.f) * s1; r1.y = fmaxf(acc1.y, 0.f) * s1;
            r1.z = fmaxf(acc1.z, 0.f) * s1; r1.w = fmaxf(acc1.w, 0.f) * s1;
            *(float4*)&dst[(g0 + m) * 64 + c4] = r0;
            *(float4*)&dst[(g0 + m + 16) * 64 + c4] = r1;
        }
        __syncthreads();
    }
}

// ---------------- LSTM layer-0 input projection: outer-product tiling --------
// Tile = 32 rows x 256 gates; thread computes 8 rows x 4 gates (2 gate-pairs).
// W stored gate-pair-packed u64t with stride-65 rows (8B-aligned; odd rows are
// NOT 16B-aligned, so odd-row loads use two LDS.64 instead of ulonglong2).
#define WGP_STRIDE 65
__global__ void __launch_bounds__(256) k_xproj(const float* __restrict__ Wih,
                                               const float* __restrict__ bih,
                                               const float* __restrict__ bhh) {
    extern __shared__ __align__(16) char smraw[];
    u64t* sWgp  = (u64t*)smraw;                  // 128 * 65 = 8320 u64t
    u64t* sxdup = sWgp + 128 * WGP_STRIDE;       // 32 * 64 = 2048 u64t
    u64t* sBgp  = sxdup + 2048;                  // 128 u64t
    int tid = threadIdx.x;
    int gq = tid & 63;        // gate-quad: gates 4gq..4gq+3
    int rq = tid >> 6;        // row-octet: rows 8rq..8rq+7

    for (int i = tid; i < 128 * 64; i += 256) {
        int gp = i >> 6, j = i & 63;
        sWgp[gp * WGP_STRIDE + j] = pack2(Wih[(2 * gp) * 64 + j], Wih[(2 * gp + 1) * 64 + j]);
    }
    if (tid < 128)
        sBgp[tid] = pack2(bih[2 * tid] + bhh[2 * tid], bih[2 * tid + 1] + bhh[2 * tid + 1]);
    __syncthreads();

    const u64t* wrow0 = &sWgp[(2 * gq) * WGP_STRIDE];       // 16B-aligned rows
    const u64t* wrow1 = &sWgp[(2 * gq + 1) * WGP_STRIDE];   // 8B-aligned only
    u64t bg0 = sBgp[2 * gq], bg1 = sBgp[2 * gq + 1];

#pragma unroll 1
    for (int tile = blockIdx.x; tile < NTILE; tile += gridDim.x) {
        int g0 = tile * 32;
        // build dup-packed x: 32 rows x 64
#pragma unroll
        for (int k = 0; k < 2; k++) {
            int i4 = tid + k * 256;           // 512 float4 total
            int r = i4 >> 4, j4 = i4 & 15;
            float4 v = *(const float4*)&g_fB[(g0 + r) * 64 + j4 * 4];
            sxdup[r * 64 + j4 * 4 + 0] = pack2(v.x, v.x);
            sxdup[r * 64 + j4 * 4 + 1] = pack2(v.y, v.y);
            sxdup[r * 64 + j4 * 4 + 2] = pack2(v.z, v.z);
            sxdup[r * 64 + j4 * 4 + 3] = pack2(v.w, v.w);
        }
        __syncthreads();
        u64t acc[8][2];
#pragma unroll
        for (int r = 0; r < 8; r++) { acc[r][0] = bg0; acc[r][1] = bg1; }
#pragma unroll 4
        for (int j2 = 0; j2 < 32; j2++) {
            ulonglong2 w0 = *(const ulonglong2*)&wrow0[j2 * 2];   // aligned
            u64t w1x = wrow1[j2 * 2];                             // LDS.64 pair
            u64t w1y = wrow1[j2 * 2 + 1];
#pragma unroll
            for (int r = 0; r < 8; r++) {
                ulonglong2 xv = *(const ulonglong2*)&sxdup[(8 * rq + r) * 64 + j2 * 2];
                ffma2(acc[r][0], w0.x, xv.x);
                ffma2(acc[r][0], w0.y, xv.y);
                ffma2(acc[r][1], w1x, xv.x);
                ffma2(acc[r][1], w1y, xv.y);
            }
        }
        u64t* outp = (u64t*)g_xp;
#pragma unroll
        for (int r = 0; r < 8; r++) {
            ulonglong2 st;
            st.x = acc[r][0]; st.y = acc[r][1];
            *(ulonglong2*)&outp[(u64t)(g0 + 8 * rq + r) * 128 + 2 * gq] = st;
        }
        __syncthreads();
    }
}

// ---------------- fused 2-layer LSTM + output projection (NB=14/block) ------
__device__ __forceinline__ float sigf(float x) { return 1.f / (1.f + __expf(-x)); }
__device__ __forceinline__ float tanhfast(float x) { return 1.f - 2.f / (__expf(2.f * x) + 1.f); }

__global__ void __launch_bounds__(256, 1) k_lstm(
    const float* __restrict__ Whh0,
    const float* __restrict__ Wih1, const float* __restrict__ Whh1,
    const float* __restrict__ bih1, const float* __restrict__ bhh1,
    const float* __restrict__ Wout, const float* __restrict__ bout,
    float* __restrict__ out)
{
    extern __shared__ float sm[];
    float* sW0  = sm;                  // 16384
    float* sWi1 = sm + 16384;          // 16384
    float* sW1  = sm + 32768;          // 16384
    float* sh0  = sm + 49152;          // NB*64 = 896
    float* sh1  = sh0 + NB * 64;       // 896
    float* sg   = sh1 + NB * 64;       // NB*256 = 3584
    float* sB1  = sg + NB * 256;       // 256

    int tid = threadIdx.x;
    for (int i = tid; i < NG * HID; i += 256) {
        int r = i >> 6, c = i & 63;
        int pos = r * 64 + (((c >> 2) ^ (r & 15)) << 2) + (c & 3);
        sW0[pos]  = Whh0[i];
        sWi1[pos] = Wih1[i];
        sW1[pos]  = Whh1[i];
    }
    sB1[tid] = bih1[tid] + bhh1[tid];
    for (int i = tid; i < NB * 64; i += 256) { sh0[i] = 0.f; sh1[i] = 0.f; }
    int gtype = tid >> 6;   // 0:i 1:f 2:g 3:o
    int wbase = tid * 64;
    int wrot  = tid & 15;
    __syncthreads();
    u64t b1p = pack2(sB1[tid], 0.f);

    int n0 = blockIdx.x * NB;
    float c0[4] = {0.f, 0.f, 0.f, 0.f};
    float c1[4] = {0.f, 0.f, 0.f, 0.f};

#pragma unroll 1
    for (int t = 0; t < WIN; t++) {
        // ---- layer 0 gates ----
        u64t acc[NB];
#pragma unroll
        for (int nn = 0; nn < NB; nn++) {
            int n = n0 + nn;
            int nc = (n < NODES) ? n : (NODES - 1);
            acc[nn] = pack2(g_xp[(t * NODES + nc) * NG + tid], 0.f);
        }
#pragma unroll 8
        for (int j4 = 0; j4 < 16; j4++) {
            ulonglong2 wv = *(const ulonglong2*)&sW0[wbase + ((j4 ^ wrot) << 2)];
#pragma unroll
            for (int nn = 0; nn < NB; nn++) {
                ulonglong2 h = *(const ulonglong2*)&sh0[nn * 64 + j4 * 4];
                ffma2(acc[nn], wv.x, h.x);
                ffma2(acc[nn], wv.y, h.y);
            }
        }
#pragma unroll
        for (int nn = 0; nn < NB; nn++) {
            float v = hsum2(acc[nn]);
            sg[nn * 256 + tid] = (gtype == 2) ? tanhfast(v) : sigf(v);
        }
        __syncthreads();
#pragma unroll
        for (int r = 0; r < 4; r++) {
            int idx = tid + 256 * r;
            if (idx < NB * 64) {
                int nn = idx >> 6, e = idx & 63;
                float gi = sg[nn * 256 + e],       gf = sg[nn * 256 + 64 + e];
                float gg = sg[nn * 256 + 128 + e], go = sg[nn * 256 + 192 + e];
                c0[r] = gf * c0[r] + gi * gg;
                sh0[idx] = go * tanhfast(c0[r]);
            }
        }
        __syncthreads();
        // ---- layer 1 gates ----
#pragma unroll
        for (int nn = 0; nn < NB; nn++) acc[nn] = b1p;
#pragma unroll 8
        for (int j4 = 0; j4 < 16; j4++) {
            int wo = (j4 ^ wrot) << 2;
            ulonglong2 wi = *(const ulonglong2*)&sWi1[wbase + wo];
            ulonglong2 wh = *(const ulonglong2*)&sW1[wbase + wo];
#pragma unroll
            for (int nn = 0; nn < NB; nn++) {
                ulonglong2 h0 = *(const ulonglong2*)&sh0[nn * 64 + j4 * 4];
                ulonglong2 h1 = *(const ulonglong2*)&sh1[nn * 64 + j4 * 4];
                ffma2(acc[nn], wi.x, h0.x);
                ffma2(acc[nn], wi.y, h0.y);
                ffma2(acc[nn], wh.x, h1.x);
                ffma2(acc[nn], wh.y, h1.y);
            }
        }
#pragma unroll
        for (int nn = 0; nn < NB; nn++) {
            float v = hsum2(acc[nn]);
            sg[nn * 256 + tid] = (gtype == 2) ? tanhfast(v) : sigf(v);
        }
        __syncthreads();
#pragma unroll
        for (int r = 0; r < 4; r++) {
            int idx = tid + 256 * r;
            if (idx < NB * 64) {
                int nn = idx >> 6, e = idx & 63;
                float gi = sg[nn * 256 + e],       gf = sg[nn * 256 + 64 + e];
                float gg = sg[nn * 256 + 128 + e], go = sg[nn * 256 + 192 + e];
                c1[r] = gf * c1[r] + gi * gg;
                sh1[idx] = go * tanhfast(c1[r]);
            }
        }
        __syncthreads();
    }
    // ---- output projection: 14 nodes x 96 outputs ----
#pragma unroll 1
    for (int i = tid; i < NB * 96; i += 256) {
        int nn = i / 96, o = i - nn * 96;
        int n = n0 + nn;
        if (n < NODES) {
            float a = bout[o];
#pragma unroll
            for (int k = 0; k < 64; k++)
                a += sh1[nn * 64 + k] * Wout[k * 96 + o];
            out[n * 96 + o] = a;
        }
    }
}

// ---------------- launcher ---------------------------------------------------
extern "C" void kernel_launch(void* const* d_in, const int* in_sizes, int n_in,
                              void* d_out, int out_size) {
    const float* x    = (const float*)d_in[0];
    const int*   ei   = (const int*)  d_in[1];
    const float* W1   = (const float*)d_in[2];
    const float* b1   = (const float*)d_in[3];
    const float* W2   = (const float*)d_in[4];
    const float* b2   = (const float*)d_in[5];
    const float* W3   = (const float*)d_in[6];
    const float* b3   = (const float*)d_in[7];
    const float* W4   = (const float*)d_in[8];
    const float* b4   = (const float*)d_in[9];
    const float* Wih0 = (const float*)d_in[10];
    const float* Whh0 = (const float*)d_in[11];
    const float* bih0 = (const float*)d_in[12];
    const float* bhh0 = (const float*)d_in[13];
    const float* Wih1 = (const float*)d_in[14];
    const float* Whh1 = (const float*)d_in[15];
    const float* bih1 = (const float*)d_in[16];
    const float* bhh1 = (const float*)d_in[17];
    const float* Wout = (const float*)d_in[18];
    const float* bout = (const float*)d_in[19];
    float* out = (float*)d_out;

    const int XP_SMEM   = (128 * WGP_STRIDE + 2048 + 128) * 8;                // 83968
    const int LSTM_SMEM = (3 * 16384 + NB * 64 * 2 + NB * 256 + 256) * 4;     // 219136
    cudaFuncSetAttribute(k_xproj, cudaFuncAttributeMaxDynamicSharedMemorySize, XP_SMEM);
    cudaFuncSetAttribute(k_lstm,  cudaFuncAttributeMaxDynamicSharedMemorySize, LSTM_SMEM);

    // graph preprocessing (scanB merged into scanC)
    k_zero_deg<<<188, 256>>>();
    k_count<<<3000, 256>>>(ei);
    k_scanA<<<188, 256>>>();
    k_scanC<<<188, 256>>>(x);
    k_fill<<<3000, 256>>>(ei);

    // GCN stack (fused aggregate + GEMM, double-buffered A/B)
    k_layer1<<<750, 256>>>(W1, b1);                  // xs -> A
    k_layer64<true,  true ><<<750, 256>>>(W2, b2);   // A -> B
    k_layer64<false, true ><<<750, 256>>>(W3, b3);   // B -> A
    k_layer64<true,  false><<<750, 256>>>(W4, b4);   // A -> B (unscaled)

    // LSTM
    k_xproj<<<750, 256, XP_SMEM>>>(Wih0, bih0, bhh0);
    k_lstm<<<NBLK, 256, LSTM_SMEM>>>(Whh0, Wih1, Whh1, bih1, bhh1, Wout, bout, out);
}